// round 2
// baseline (speedup 1.0000x reference)
#include <cuda_runtime.h>
#include <cuda_bf16.h>
#include <math.h>

// Problem constants (from reference): B=8, N=256, MAX_DIM=2, D=4, EPS=1e-8
#define BQ 8
#define NP 256
#define NCELL 16   // B * MAX_DIM

__device__ float g_partial[NCELL];

// One block per (batch, dim) cell. 512 threads: lower half handles set1
// projection+sort, upper half handles set2. Bitonic sort of 256 floats in
// shared memory, then L1 diff of the two sorted sequences.
// Key math: cost matrix is |proj(a)_i - proj(b)_j| (1D L1), so the optimal
// linear assignment total == sum |sorted(a)_i - sorted(b)_i|; the 2B LAPs
// come in transpose pairs with equal totals -> factor 2.
__global__ __launch_bounds__(512)
void hungarian_1d_kernel(const float* __restrict__ set1,
                         const float* __restrict__ set2) {
    __shared__ float sa[NP];
    __shared__ float sb[NP];
    __shared__ float red[NP];

    const int cell = blockIdx.x;          // 0..15
    const int b    = cell >> 1;
    const int dim  = cell & 1;
    const float fdim = (float)dim;

    const int tid = threadIdx.x;          // 0..511
    const int n   = tid & (NP - 1);       // element index 0..255
    const bool lower = (tid < NP);

    // --- projection ---
    if (lower) {
        const float4 p = ((const float4*)set1)[(size_t)b * NP + n];
        bool m = (p.z == fdim);
        float xm = m ? p.x : 0.0f;
        float ym = m ? p.y : 0.0f;
        sa[n] = xm + sqrtf(ym + 1e-8f) * 0.5f;
    } else {
        const float4 p = ((const float4*)set2)[(size_t)b * NP + n];
        // jnp.argmax over (c2, c3): first max wins -> label 1 iff c3 > c2
        int label = (p.w > p.z) ? 1 : 0;
        bool m = (label == dim);
        float xm = m ? p.x : 0.0f;
        float ym = m ? p.y : 0.0f;
        sb[n] = xm + sqrtf(ym + 1e-8f) * 0.5f;
    }
    __syncthreads();

    // --- bitonic sort: both arrays concurrently (each by one half-block) ---
    float* s = lower ? sa : sb;
    #pragma unroll 1
    for (int k = 2; k <= NP; k <<= 1) {
        #pragma unroll 1
        for (int j = k >> 1; j > 0; j >>= 1) {
            int ixj = n ^ j;
            if (ixj > n) {
                float v0 = s[n];
                float v1 = s[ixj];
                bool asc = ((n & k) == 0);
                if ((v0 > v1) == asc) {   // out of order -> swap
                    s[n]   = v1;
                    s[ixj] = v0;
                }
            }
            __syncthreads();
        }
    }

    // --- L1 diff of sorted sequences, tree-reduce ---
    if (lower) {
        red[n] = fabsf(sa[n] - sb[n]);
    }
    __syncthreads();
    #pragma unroll
    for (int off = 128; off > 0; off >>= 1) {
        if (tid < off) red[tid] += red[tid + off];
        __syncthreads();
    }
    if (tid == 0) {
        // two identical LAPs (k and k+B are transposes), each averaged over N
        g_partial[cell] = red[0] * (2.0f / (float)NP);
    }
}

__global__ void finalize_kernel(float* __restrict__ out) {
    float t = 0.0f;
    #pragma unroll
    for (int i = 0; i < NCELL; i++) t += g_partial[i];
    out[0] = t;
}

extern "C" void kernel_launch(void* const* d_in, const int* in_sizes, int n_in,
                              void* d_out, int out_size) {
    const float* set1 = (const float*)d_in[0];
    const float* set2 = (const float*)d_in[1];
    float* out = (float*)d_out;

    hungarian_1d_kernel<<<NCELL, 512>>>(set1, set2);
    finalize_kernel<<<1, 1>>>(out);
}